// round 13
// baseline (speedup 1.0000x reference)
#include <cuda_runtime.h>
#include <cuda_bf16.h>
#include <cuda_fp16.h>
#include <cstdint>

// ============================================================================
// Fused SDPA with attn-matrix output.
// R13: KT 64 -> 128 (half the tiles, half the barrier/pipeline overhead in
//      both loop kernels; 2 CTAs/SM attn, 3 CTAs/SM rowsum preserved).
//   convert_kernel: Q(/8),K,V -> fp16; mask -> float.
//   rowsum_kernel:  fp16 QK -> exp -> rowsum -> 1/rowsum.
//   attn_kernel:    fp16 QK -> p=mask*exp*inv (NORMALIZED, __stwt to attn)
//                   -> PV fp16 -> out written as-is.
// ============================================================================

namespace {

constexpr int S_  = 2048;
constexpr int D_  = 64;
constexpr int BH_ = 32;          // B*H
constexpr int TQ_ = 128;         // queries per CTA
constexpr int KT_ = 128;         // keys per stage
constexpr int NKT_ = S_ / KT_;   // 16 tiles
constexpr int NCH_ = KT_ / 16;   // 8 chunks per tile
constexpr int THREADS_ = 256;    // 8 warps
constexpr int ROWP_ = 72;        // padded 16-bit row (144B) -> conflict-free LDSM
constexpr int NELEM_ = BH_ * S_ * D_;   // 4.19M per tensor

// ---- scratch ----
__device__ __half g_qf[NELEM_];                 // Q/8 fp16
__device__ __half g_kf[NELEM_];                 // K fp16
__device__ __half g_v[NELEM_];                  // V fp16
__device__ float g_mf[2 * S_];
__device__ float g_inv[BH_ * S_];               // 1/rowsum per (bh, row)

// ---- attn kernel smem (3 stages; Q overlays stage 1 in prologue) ----
constexpr int KF_  = 0;
constexpr int VV_  = KF_ + KT_ * ROWP_ * 2;          // 18432
constexpr int MSK_ = VV_ + KT_ * ROWP_ * 2;          // 36864 (within stage)
constexpr int STG_SZ = MSK_ + KT_ * 4;               // 37376
constexpr int SQ_OFF = STG_SZ;                       // Q fp16 (18432 <= STG_SZ)
constexpr int SMEM_BYTES = 3 * STG_SZ;               // 112128 (<= 114688: 2 CTAs)

// ---- rowsum kernel smem (separate Q region + 3 stages) ----
constexpr int RQ_OFF = 0;                            // Q fp16: 18432
constexpr int RSTG_OFF = TQ_ * ROWP_ * 2;            // 18432
constexpr int RKF_ = 0;
constexpr int RMSK_ = KT_ * ROWP_ * 2;               // 18432 (within stage)
constexpr int RSTG_SZ = RMSK_ + KT_ * 4;             // 18944
constexpr int RSMEM_BYTES = RSTG_OFF + 3 * RSTG_SZ;  // 75264 (x3 CTAs = 225792)

__device__ __forceinline__ uint32_t smem_u32(const void* p) {
    return (uint32_t)__cvta_generic_to_shared(p);
}
__device__ __forceinline__ void cp16(uint32_t dst, const void* src) {
    asm volatile("cp.async.cg.shared.global [%0], [%1], 16;" :: "r"(dst), "l"(src));
}
#define CP_COMMIT() asm volatile("cp.async.commit_group;" ::: "memory")
#define CP_WAIT(n)  asm volatile("cp.async.wait_group %0;" :: "n"(n) : "memory")

__device__ __forceinline__ void ldsm_x4(uint32_t a[4], uint32_t addr) {
    asm volatile("ldmatrix.sync.aligned.m8n8.x4.shared.b16 {%0,%1,%2,%3}, [%4];"
                 : "=r"(a[0]), "=r"(a[1]), "=r"(a[2]), "=r"(a[3]) : "r"(addr));
}
__device__ __forceinline__ void ldsm_x4t(uint32_t a[4], uint32_t addr) {
    asm volatile("ldmatrix.sync.aligned.m8n8.x4.trans.shared.b16 {%0,%1,%2,%3}, [%4];"
                 : "=r"(a[0]), "=r"(a[1]), "=r"(a[2]), "=r"(a[3]) : "r"(addr));
}
__device__ __forceinline__ void mma_f16(float c[4], const uint32_t a[4], const uint32_t b[2]) {
    asm volatile(
        "mma.sync.aligned.m16n8k16.row.col.f32.f16.f16.f32 "
        "{%0,%1,%2,%3}, {%4,%5,%6,%7}, {%8,%9}, {%0,%1,%2,%3};"
        : "+f"(c[0]), "+f"(c[1]), "+f"(c[2]), "+f"(c[3])
        : "r"(a[0]), "r"(a[1]), "r"(a[2]), "r"(a[3]), "r"(b[0]), "r"(b[1]));
}
__device__ __forceinline__ uint2 pack_f16x4(float4 v) {
    __half2 a = __floats2half2_rn(v.x, v.y);
    __half2 b = __floats2half2_rn(v.z, v.w);
    return make_uint2(*reinterpret_cast<uint32_t*>(&a), *reinterpret_cast<uint32_t*>(&b));
}
__device__ __forceinline__ uint32_t h2_of(float x, float y) {
    __half2 h = __floats2half2_rn(x, y);
    return *reinterpret_cast<uint32_t*>(&h);
}

// ---------------------------------------------------------------------------
__global__ void __launch_bounds__(256)
convert_kernel(const float* __restrict__ q, const float* __restrict__ k,
               const float* __restrict__ v, const int* __restrict__ m) {
    const int N4 = NELEM_ / 4;
    const int stride = gridDim.x * blockDim.x;
    for (int j = blockIdx.x * blockDim.x + threadIdx.x; j < N4; j += stride) {
        float4 x = reinterpret_cast<const float4*>(q)[j];
        x.x *= 0.125f; x.y *= 0.125f; x.z *= 0.125f; x.w *= 0.125f;
        reinterpret_cast<uint2*>(g_qf)[j] = pack_f16x4(x);
        reinterpret_cast<uint2*>(g_kf)[j] = pack_f16x4(reinterpret_cast<const float4*>(k)[j]);
        reinterpret_cast<uint2*>(g_v)[j]  = pack_f16x4(reinterpret_cast<const float4*>(v)[j]);
    }
    for (int j = blockIdx.x * blockDim.x + threadIdx.x; j < 2 * S_; j += stride)
        g_mf[j] = m[j] ? 1.f : 0.f;
}

// ---------------------------------------------------------------------------
// rowsum_kernel: fp16 QK -> exp -> rowsum; writes 1/rowsum.
// ---------------------------------------------------------------------------
__device__ __forceinline__ void cp_tile_k16(uint32_t stg, size_t kvoff,
                                            size_t moff, int tid) {
#pragma unroll
    for (int i = 0; i < 4; i++) {
        int c = tid + THREADS_ * i;                 // 0..1023 (128 rows x 8 chunks)
        int row = c >> 3, j = c & 7;
        cp16(stg + RKF_ + row * 144 + j * 16, g_kf + kvoff + row * 64 + j * 8);
    }
    if (tid < 32) cp16(stg + RMSK_ + tid * 16, g_mf + moff + tid * 4);
}

__global__ void __launch_bounds__(THREADS_, 3)
rowsum_kernel() {
    extern __shared__ char smem[];
    const uint32_t sb = smem_u32(smem);

    const int qt = blockIdx.x;
    const int bh = blockIdx.y;
    const int tid = threadIdx.x;
    const int wid = tid >> 5;
    const int lane = tid & 31;
    const int b = bh >> 4;

    const size_t base = (size_t)bh * S_ * D_;
    const size_t qoff = base + (size_t)qt * TQ_ * D_;
    const size_t moff = (size_t)b * S_;

    const uint32_t stg[3] = {sb + RSTG_OFF, sb + RSTG_OFF + RSTG_SZ,
                             sb + RSTG_OFF + 2 * RSTG_SZ};

    // Prologue: Q fp16 (1024 chunks) + tiles 0,1
    {
#pragma unroll
        for (int i = 0; i < 4; i++) {
            int c = tid + THREADS_ * i;             // 0..1023
            int row = c >> 3, j = c & 7;
            cp16(sb + RQ_OFF + row * 144 + j * 16, g_qf + qoff + row * 64 + j * 8);
        }
        cp_tile_k16(stg[0], base, moff, tid);
        CP_COMMIT();
        cp_tile_k16(stg[1], base + KT_ * D_, moff + KT_, tid);
        CP_COMMIT();
    }
    CP_WAIT(1);
    __syncthreads();

    // Q fragments
    uint32_t qf[4][4];
    {
        int r = wid * 16 + (lane & 15);
        int ch = (lane >> 4) * 8;
        const __half* sQ = (const __half*)(smem + RQ_OFF);
#pragma unroll
        for (int ds = 0; ds < 4; ds++)
            ldsm_x4(qf[ds], smem_u32(&sQ[r * ROWP_ + ds * 16 + ch]));
    }

    const uint32_t koff = (((lane & 7) + ((lane >> 4) << 3)) * ROWP_) * 2 + ((lane >> 3) & 1) * 16;
    const int rsb = ROWP_ * 2;
    float rs0 = 0.f, rs1 = 0.f;

    int s = 0, sp2 = 2;
#pragma unroll 1
    for (int kt = 0; kt < NKT_; kt++) {
        if (kt > 0) { CP_WAIT(1); __syncthreads(); }
        if (kt + 2 < NKT_)
            cp_tile_k16(stg[sp2], base + (size_t)(kt + 2) * KT_ * D_,
                        moff + (kt + 2) * KT_, tid);
        CP_COMMIT();

        const uint32_t bkf = stg[s] + RKF_ + koff;
        const float* msk = (const float*)(smem + RSTG_OFF + s * RSTG_SZ + RMSK_);

#pragma unroll
        for (int nc = 0; nc < NCH_; nc++) {
            const int n0 = nc * 16;
            float c0[4] = {0.f, 0.f, 0.f, 0.f};
            float c1[4] = {0.f, 0.f, 0.f, 0.f};
#pragma unroll
            for (int ds = 0; ds < 4; ds++) {
                uint32_t k4[4];
                ldsm_x4(k4, bkf + n0 * rsb + ds * 32);
                mma_f16(c0, qf[ds], k4);
                mma_f16(c1, qf[ds], k4 + 2);
            }
            int kc = n0 + ((lane & 3) << 1);
            float m00 = msk[kc],     m01 = msk[kc + 1];
            float m10 = msk[kc + 8], m11 = msk[kc + 9];
            rs0 += m00 * __expf(c0[0]) + m01 * __expf(c0[1])
                 + m10 * __expf(c1[0]) + m11 * __expf(c1[1]);
            rs1 += m00 * __expf(c0[2]) + m01 * __expf(c0[3])
                 + m10 * __expf(c1[2]) + m11 * __expf(c1[3]);
        }
        sp2 = s;
        s = (s == 2) ? 0 : s + 1;
    }

    rs0 += __shfl_xor_sync(0xffffffffu, rs0, 1);
    rs0 += __shfl_xor_sync(0xffffffffu, rs0, 2);
    rs1 += __shfl_xor_sync(0xffffffffu, rs1, 1);
    rs1 += __shfl_xor_sync(0xffffffffu, rs1, 2);
    if ((lane & 3) == 0) {
        int r = qt * TQ_ + wid * 16 + (lane >> 2);
        g_inv[bh * S_ + r]     = 1.f / rs0;
        g_inv[bh * S_ + r + 8] = 1.f / rs1;
    }
}

// ---------------------------------------------------------------------------
// Main attention kernel: writes NORMALIZED attn directly (no sweep).
// ---------------------------------------------------------------------------
__device__ __forceinline__ void cp_tile_kv(uint32_t stg, size_t kvoff,
                                           size_t moff, int tid) {
#pragma unroll
    for (int i = 0; i < 4; i++) {
        int c = tid + THREADS_ * i;                 // 0..1023
        int row = c >> 3, j = c & 7;
        uint32_t so = row * 144 + j * 16;
        size_t go = kvoff + row * 64 + j * 8;
        cp16(stg + KF_ + so, g_kf + go);
        cp16(stg + VV_ + so, g_v + go);
    }
    if (tid < 32) cp16(stg + MSK_ + tid * 16, g_mf + moff + tid * 4);
}

__global__ void __launch_bounds__(THREADS_, 2)
attn_kernel(float* __restrict__ Out) {
    extern __shared__ char smem[];
    const uint32_t sb = smem_u32(smem);

    const int qt = blockIdx.x;
    const int bh = blockIdx.y;
    const int tid = threadIdx.x;
    const int wid = tid >> 5;
    const int lane = tid & 31;
    const int b = bh >> 4;

    const size_t base = (size_t)bh * S_ * D_;
    const size_t qoff = base + (size_t)qt * TQ_ * D_;
    const size_t moff = (size_t)b * S_;
    float* Og = Out + qoff;
    float* Ag = Out + (size_t)BH_ * S_ * D_ + (size_t)bh * S_ * S_ + (size_t)qt * TQ_ * S_;

    const uint32_t stg[3] = {sb, sb + STG_SZ, sb + 2 * STG_SZ};

    // Prologue: Q (overlaying stage 1), tile 0
    {
#pragma unroll
        for (int i = 0; i < 4; i++) {
            int c = tid + THREADS_ * i;             // 0..1023
            int row = c >> 3, j = c & 7;
            cp16(sb + SQ_OFF + row * 144 + j * 16, g_qf + qoff + row * 64 + j * 8);
        }
        CP_COMMIT();                                // group: Q
        cp_tile_kv(stg[0], base, moff, tid);
        CP_COMMIT();                                // group: tile 0
    }
    CP_WAIT(1);                                     // Q arrived
    __syncthreads();

    // Q fragments (fp16)
    uint32_t aH[4][4];
    {
        int r = wid * 16 + (lane & 15);
        int ch = (lane >> 4) * 8;
        const __half* sQ = (const __half*)(smem + SQ_OFF);
#pragma unroll
        for (int ds = 0; ds < 4; ds++)
            ldsm_x4(aH[ds], smem_u32(&sQ[r * ROWP_ + ds * 16 + ch]));
    }
    __syncthreads();    // stage 1 free
    cp_tile_kv(stg[1], base + KT_ * D_, moff + KT_, tid);
    CP_COMMIT();                                    // group: tile 1

    const uint32_t koff = (((lane & 7) + ((lane >> 4) << 3)) * ROWP_) * 2 + ((lane >> 3) & 1) * 16;
    const uint32_t voff = (lane & 15) * ROWP_ * 2 + (lane >> 4) * 16;
    const int rsb = ROWP_ * 2;
    const int qr0 = wid * 16 + (lane >> 2);

    // Per-row inverse rowsums (same fp16 QK as rowsum_kernel -> rows sum to 1)
    const float inv0 = g_inv[bh * S_ + qt * TQ_ + qr0];
    const float inv1 = g_inv[bh * S_ + qt * TQ_ + qr0 + 8];

    float o[8][4];
#pragma unroll
    for (int dn = 0; dn < 8; dn++)
#pragma unroll
        for (int c = 0; c < 4; c++) o[dn][c] = 0.f;

    int s = 0, sp2 = 2;
#pragma unroll 1
    for (int kt = 0; kt < NKT_; kt++) {
        CP_WAIT(1);
        __syncthreads();

        if (kt + 2 < NKT_)
            cp_tile_kv(stg[sp2], base + (size_t)(kt + 2) * KT_ * D_,
                       moff + (kt + 2) * KT_, tid);
        CP_COMMIT();

        const uint32_t bkf = stg[s] + KF_ + koff;
        const uint32_t bvv = stg[s] + VV_ + voff;
        const float* msk = (const float*)(smem + (s * STG_SZ + MSK_));

        // QK for chunk 0 (single-term fp16)
        float c0[4] = {0.f, 0.f, 0.f, 0.f}, c1[4] = {0.f, 0.f, 0.f, 0.f};
#pragma unroll
        for (int ds = 0; ds < 4; ds++) {
            uint32_t k4[4];
            ldsm_x4(k4, bkf + ds * 32);
            mma_f16(c0, aH[ds], k4);
            mma_f16(c1, aH[ds], k4 + 2);
        }

#pragma unroll
        for (int nc = 0; nc < NCH_; nc++) {
            const int n0 = nc * 16;
            // exp + normalize (final attn values)
            float pn[2][4];
            {
                int kc = n0 + ((lane & 3) << 1);
                float m00 = msk[kc] * inv0,     m01 = msk[kc + 1] * inv0;
                float m10 = msk[kc + 8] * inv0, m11 = msk[kc + 9] * inv0;
                float n00 = msk[kc] * inv1,     n01 = msk[kc + 1] * inv1;
                float n10 = msk[kc + 8] * inv1, n11 = msk[kc + 9] * inv1;
                pn[0][0] = m00 * __expf(c0[0]);
                pn[0][1] = m01 * __expf(c0[1]);
                pn[0][2] = n00 * __expf(c0[2]);
                pn[0][3] = n01 * __expf(c0[3]);
                pn[1][0] = m10 * __expf(c1[0]);
                pn[1][1] = m11 * __expf(c1[1]);
                pn[1][2] = n10 * __expf(c1[2]);
                pn[1][3] = n11 * __expf(c1[3]);
            }

            // QK for chunk nc+1 (covers exp latency)
            if (nc < NCH_ - 1) {
#pragma unroll
                for (int i = 0; i < 4; i++) { c0[i] = 0.f; c1[i] = 0.f; }
#pragma unroll
                for (int ds = 0; ds < 4; ds++) {
                    uint32_t k4[4];
                    ldsm_x4(k4, bkf + (n0 + 16) * rsb + ds * 32);
                    mma_f16(c0, aH[ds], k4);
                    mma_f16(c1, aH[ds], k4 + 2);
                }
            }

            // pack normalized p (single fp16)
            uint32_t ph[4];
            ph[0] = h2_of(pn[0][0], pn[0][1]);
            ph[1] = h2_of(pn[0][2], pn[0][3]);
            ph[2] = h2_of(pn[1][0], pn[1][1]);
            ph[3] = h2_of(pn[1][2], pn[1][3]);

            // PV (single-term fp16)
#pragma unroll
            for (int dp = 0; dp < 4; dp++) {
                uint32_t v4[4];
                ldsm_x4t(v4, bvv + n0 * rsb + dp * 32);
                mma_f16(o[2 * dp],     ph, v4);
                mma_f16(o[2 * dp + 1], ph, v4 + 2);
            }

            // Final attn store (streaming: never re-read)
#pragma unroll
            for (int nt = 0; nt < 2; nt++) {
                int col = kt * KT_ + n0 + nt * 8 + ((lane & 3) << 1);
                __stwt(reinterpret_cast<float2*>(Ag + (size_t)qr0 * S_ + col),
                       make_float2(pn[nt][0], pn[nt][1]));
                __stwt(reinterpret_cast<float2*>(Ag + (size_t)(qr0 + 8) * S_ + col),
                       make_float2(pn[nt][2], pn[nt][3]));
            }
        }

        sp2 = s;
        s = (s == 2) ? 0 : s + 1;
    }

    // out = o (p was already normalized before PV)
#pragma unroll
    for (int dn = 0; dn < 8; dn++) {
        int col = dn * 8 + ((lane & 3) << 1);
        *reinterpret_cast<float2*>(Og + (size_t)qr0 * D_ + col) =
            make_float2(o[dn][0], o[dn][1]);
        *reinterpret_cast<float2*>(Og + (size_t)(qr0 + 8) * D_ + col) =
            make_float2(o[dn][2], o[dn][3]);
    }
}

} // namespace

extern "C" void kernel_launch(void* const* d_in, const int* in_sizes, int n_in,
                              void* d_out, int out_size) {
    (void)in_sizes; (void)n_in; (void)out_size;
    const float* q = (const float*)d_in[0];
    const float* k = (const float*)d_in[1];
    const float* v = (const float*)d_in[2];
    const int*   m = (const int*)d_in[3];
    float* out = (float*)d_out;

    convert_kernel<<<2048, 256>>>(q, k, v, m);

    cudaFuncSetAttribute(rowsum_kernel, cudaFuncAttributeMaxDynamicSharedMemorySize, RSMEM_BYTES);
    dim3 grid(S_ / TQ_, BH_);
    rowsum_kernel<<<grid, THREADS_, RSMEM_BYTES>>>();

    cudaFuncSetAttribute(attn_kernel, cudaFuncAttributeMaxDynamicSharedMemorySize, SMEM_BYTES);
    attn_kernel<<<grid, THREADS_, SMEM_BYTES>>>(out);
}

// round 14
// speedup vs baseline: 1.0362x; 1.0362x over previous
#include <cuda_runtime.h>
#include <cuda_bf16.h>
#include <cuda_fp16.h>
#include <cstdint>

// ============================================================================
// Fused SDPA with attn-matrix output.
// R14: revert to KT=64 (R13's KT=128 regressed); attn kernel pipeline
//      deepened to 4 stages / prefetch distance 3 / CP_WAIT(2); Q in its own
//      smem region. rowsum kernel = R12 form (3 stages, 3 CTAs/SM).
//   convert_kernel: Q(/8),K,V -> fp16; mask -> float.
//   rowsum_kernel:  fp16 QK -> exp -> rowsum -> 1/rowsum.
//   attn_kernel:    fp16 QK -> p=mask*exp*inv (NORMALIZED, __stwt to attn)
//                   -> PV fp16 -> out written as-is.
// ============================================================================

namespace {

constexpr int S_  = 2048;
constexpr int D_  = 64;
constexpr int BH_ = 32;          // B*H
constexpr int TQ_ = 128;         // queries per CTA
constexpr int KT_ = 64;          // keys per stage
constexpr int NKT_ = S_ / KT_;   // 32 tiles
constexpr int NCH_ = KT_ / 16;   // 4 chunks per tile
constexpr int THREADS_ = 256;    // 8 warps
constexpr int ROWP_ = 72;        // padded 16-bit row (144B) -> conflict-free LDSM
constexpr int NELEM_ = BH_ * S_ * D_;   // 4.19M per tensor

// ---- scratch ----
__device__ __half g_qf[NELEM_];                 // Q/8 fp16
__device__ __half g_kf[NELEM_];                 // K fp16
__device__ __half g_v[NELEM_];                  // V fp16
__device__ float g_mf[2 * S_];
__device__ float g_inv[BH_ * S_];               // 1/rowsum per (bh, row)

// ---- attn kernel smem: 4 stages + separate Q region ----
constexpr int KF_  = 0;
constexpr int VV_  = KF_ + KT_ * ROWP_ * 2;          // 9216
constexpr int MSK_ = VV_ + KT_ * ROWP_ * 2;          // 18432 (within stage)
constexpr int STG_SZ = MSK_ + KT_ * 4;               // 18688
constexpr int NSTG_ = 4;
constexpr int SQ_OFF = NSTG_ * STG_SZ;               // 74752
constexpr int SMEM_BYTES = SQ_OFF + TQ_ * ROWP_ * 2; // 93184 (x2 CTAs fits)

// ---- rowsum kernel smem (R12 form: Q region + 3 stages) ----
constexpr int RQ_OFF = 0;                            // Q fp16: 18432
constexpr int RSTG_OFF = TQ_ * ROWP_ * 2;            // 18432
constexpr int RKF_ = 0;
constexpr int RMSK_ = KT_ * ROWP_ * 2;               // 9216 (within stage)
constexpr int RSTG_SZ = RMSK_ + KT_ * 4;             // 9472
constexpr int RSMEM_BYTES = RSTG_OFF + 3 * RSTG_SZ;  // 46848 (x3 CTAs fits)

__device__ __forceinline__ uint32_t smem_u32(const void* p) {
    return (uint32_t)__cvta_generic_to_shared(p);
}
__device__ __forceinline__ void cp16(uint32_t dst, const void* src) {
    asm volatile("cp.async.cg.shared.global [%0], [%1], 16;" :: "r"(dst), "l"(src));
}
#define CP_COMMIT() asm volatile("cp.async.commit_group;" ::: "memory")
#define CP_WAIT(n)  asm volatile("cp.async.wait_group %0;" :: "n"(n) : "memory")

__device__ __forceinline__ void ldsm_x4(uint32_t a[4], uint32_t addr) {
    asm volatile("ldmatrix.sync.aligned.m8n8.x4.shared.b16 {%0,%1,%2,%3}, [%4];"
                 : "=r"(a[0]), "=r"(a[1]), "=r"(a[2]), "=r"(a[3]) : "r"(addr));
}
__device__ __forceinline__ void ldsm_x4t(uint32_t a[4], uint32_t addr) {
    asm volatile("ldmatrix.sync.aligned.m8n8.x4.trans.shared.b16 {%0,%1,%2,%3}, [%4];"
                 : "=r"(a[0]), "=r"(a[1]), "=r"(a[2]), "=r"(a[3]) : "r"(addr));
}
__device__ __forceinline__ void mma_f16(float c[4], const uint32_t a[4], const uint32_t b[2]) {
    asm volatile(
        "mma.sync.aligned.m16n8k16.row.col.f32.f16.f16.f32 "
        "{%0,%1,%2,%3}, {%4,%5,%6,%7}, {%8,%9}, {%0,%1,%2,%3};"
        : "+f"(c[0]), "+f"(c[1]), "+f"(c[2]), "+f"(c[3])
        : "r"(a[0]), "r"(a[1]), "r"(a[2]), "r"(a[3]), "r"(b[0]), "r"(b[1]));
}
__device__ __forceinline__ uint2 pack_f16x4(float4 v) {
    __half2 a = __floats2half2_rn(v.x, v.y);
    __half2 b = __floats2half2_rn(v.z, v.w);
    return make_uint2(*reinterpret_cast<uint32_t*>(&a), *reinterpret_cast<uint32_t*>(&b));
}
__device__ __forceinline__ uint32_t h2_of(float x, float y) {
    __half2 h = __floats2half2_rn(x, y);
    return *reinterpret_cast<uint32_t*>(&h);
}

// ---------------------------------------------------------------------------
__global__ void __launch_bounds__(256)
convert_kernel(const float* __restrict__ q, const float* __restrict__ k,
               const float* __restrict__ v, const int* __restrict__ m) {
    const int N4 = NELEM_ / 4;
    const int stride = gridDim.x * blockDim.x;
    for (int j = blockIdx.x * blockDim.x + threadIdx.x; j < N4; j += stride) {
        float4 x = reinterpret_cast<const float4*>(q)[j];
        x.x *= 0.125f; x.y *= 0.125f; x.z *= 0.125f; x.w *= 0.125f;
        reinterpret_cast<uint2*>(g_qf)[j] = pack_f16x4(x);
        reinterpret_cast<uint2*>(g_kf)[j] = pack_f16x4(reinterpret_cast<const float4*>(k)[j]);
        reinterpret_cast<uint2*>(g_v)[j]  = pack_f16x4(reinterpret_cast<const float4*>(v)[j]);
    }
    for (int j = blockIdx.x * blockDim.x + threadIdx.x; j < 2 * S_; j += stride)
        g_mf[j] = m[j] ? 1.f : 0.f;
}

// ---------------------------------------------------------------------------
// rowsum_kernel: fp16 QK -> exp -> rowsum; writes 1/rowsum. (R12 form)
// ---------------------------------------------------------------------------
__device__ __forceinline__ void cp_tile_k16(uint32_t stg, size_t kvoff,
                                            size_t moff, int tid) {
#pragma unroll
    for (int i = 0; i < 2; i++) {
        int c = tid + THREADS_ * i;                 // 0..511 (64 rows x 8 chunks)
        int row = c >> 3, j = c & 7;
        cp16(stg + RKF_ + row * 144 + j * 16, g_kf + kvoff + row * 64 + j * 8);
    }
    if (tid < 16) cp16(stg + RMSK_ + tid * 16, g_mf + moff + tid * 4);
}

__global__ void __launch_bounds__(THREADS_, 3)
rowsum_kernel() {
    extern __shared__ char smem[];
    const uint32_t sb = smem_u32(smem);

    const int qt = blockIdx.x;
    const int bh = blockIdx.y;
    const int tid = threadIdx.x;
    const int wid = tid >> 5;
    const int lane = tid & 31;
    const int b = bh >> 4;

    const size_t base = (size_t)bh * S_ * D_;
    const size_t qoff = base + (size_t)qt * TQ_ * D_;
    const size_t moff = (size_t)b * S_;

    const uint32_t stg[3] = {sb + RSTG_OFF, sb + RSTG_OFF + RSTG_SZ,
                             sb + RSTG_OFF + 2 * RSTG_SZ};

    // Prologue: Q fp16 (1024 chunks) + tiles 0,1
    {
#pragma unroll
        for (int i = 0; i < 4; i++) {
            int c = tid + THREADS_ * i;             // 0..1023
            int row = c >> 3, j = c & 7;
            cp16(sb + RQ_OFF + row * 144 + j * 16, g_qf + qoff + row * 64 + j * 8);
        }
        cp_tile_k16(stg[0], base, moff, tid);
        CP_COMMIT();
        cp_tile_k16(stg[1], base + KT_ * D_, moff + KT_, tid);
        CP_COMMIT();
    }
    CP_WAIT(1);
    __syncthreads();

    // Q fragments
    uint32_t qf[4][4];
    {
        int r = wid * 16 + (lane & 15);
        int ch = (lane >> 4) * 8;
        const __half* sQ = (const __half*)(smem + RQ_OFF);
#pragma unroll
        for (int ds = 0; ds < 4; ds++)
            ldsm_x4(qf[ds], smem_u32(&sQ[r * ROWP_ + ds * 16 + ch]));
    }

    const uint32_t koff = (((lane & 7) + ((lane >> 4) << 3)) * ROWP_) * 2 + ((lane >> 3) & 1) * 16;
    const int rsb = ROWP_ * 2;
    float rs0 = 0.f, rs1 = 0.f;

    int s = 0, sp2 = 2;
#pragma unroll 1
    for (int kt = 0; kt < NKT_; kt++) {
        if (kt > 0) { CP_WAIT(1); __syncthreads(); }
        if (kt + 2 < NKT_)
            cp_tile_k16(stg[sp2], base + (size_t)(kt + 2) * KT_ * D_,
                        moff + (kt + 2) * KT_, tid);
        CP_COMMIT();

        const uint32_t bkf = stg[s] + RKF_ + koff;
        const float* msk = (const float*)(smem + RSTG_OFF + s * RSTG_SZ + RMSK_);

#pragma unroll
        for (int nc = 0; nc < NCH_; nc++) {
            const int n0 = nc * 16;
            float c0[4] = {0.f, 0.f, 0.f, 0.f};
            float c1[4] = {0.f, 0.f, 0.f, 0.f};
#pragma unroll
            for (int ds = 0; ds < 4; ds++) {
                uint32_t k4[4];
                ldsm_x4(k4, bkf + n0 * rsb + ds * 32);
                mma_f16(c0, qf[ds], k4);
                mma_f16(c1, qf[ds], k4 + 2);
            }
            int kc = n0 + ((lane & 3) << 1);
            float m00 = msk[kc],     m01 = msk[kc + 1];
            float m10 = msk[kc + 8], m11 = msk[kc + 9];
            rs0 += m00 * __expf(c0[0]) + m01 * __expf(c0[1])
                 + m10 * __expf(c1[0]) + m11 * __expf(c1[1]);
            rs1 += m00 * __expf(c0[2]) + m01 * __expf(c0[3])
                 + m10 * __expf(c1[2]) + m11 * __expf(c1[3]);
        }
        sp2 = s;
        s = (s == 2) ? 0 : s + 1;
    }

    rs0 += __shfl_xor_sync(0xffffffffu, rs0, 1);
    rs0 += __shfl_xor_sync(0xffffffffu, rs0, 2);
    rs1 += __shfl_xor_sync(0xffffffffu, rs1, 1);
    rs1 += __shfl_xor_sync(0xffffffffu, rs1, 2);
    if ((lane & 3) == 0) {
        int r = qt * TQ_ + wid * 16 + (lane >> 2);
        g_inv[bh * S_ + r]     = 1.f / rs0;
        g_inv[bh * S_ + r + 8] = 1.f / rs1;
    }
}

// ---------------------------------------------------------------------------
// Main attention kernel: 4-stage pipeline, writes NORMALIZED attn directly.
// ---------------------------------------------------------------------------
__device__ __forceinline__ void cp_tile_kv(uint32_t stg, size_t kvoff,
                                           size_t moff, int tid) {
#pragma unroll
    for (int i = 0; i < 2; i++) {
        int c = tid + THREADS_ * i;                 // 0..511
        int row = c >> 3, j = c & 7;
        uint32_t so = row * 144 + j * 16;
        size_t go = kvoff + row * 64 + j * 8;
        cp16(stg + KF_ + so, g_kf + go);
        cp16(stg + VV_ + so, g_v + go);
    }
    if (tid < 16) cp16(stg + MSK_ + tid * 16, g_mf + moff + tid * 4);
}

__global__ void __launch_bounds__(THREADS_, 2)
attn_kernel(float* __restrict__ Out) {
    extern __shared__ char smem[];
    const uint32_t sb = smem_u32(smem);

    const int qt = blockIdx.x;
    const int bh = blockIdx.y;
    const int tid = threadIdx.x;
    const int wid = tid >> 5;
    const int lane = tid & 31;
    const int b = bh >> 4;

    const size_t base = (size_t)bh * S_ * D_;
    const size_t qoff = base + (size_t)qt * TQ_ * D_;
    const size_t moff = (size_t)b * S_;
    float* Og = Out + qoff;
    float* Ag = Out + (size_t)BH_ * S_ * D_ + (size_t)bh * S_ * S_ + (size_t)qt * TQ_ * S_;

    const uint32_t stg[NSTG_] = {sb, sb + STG_SZ, sb + 2 * STG_SZ, sb + 3 * STG_SZ};

    // Prologue: Q (own region, group 0), tiles 0,1,2 (groups 1,2,3)
    {
#pragma unroll
        for (int i = 0; i < 4; i++) {
            int c = tid + THREADS_ * i;             // 0..1023
            int row = c >> 3, j = c & 7;
            cp16(sb + SQ_OFF + row * 144 + j * 16, g_qf + qoff + row * 64 + j * 8);
        }
        CP_COMMIT();                                // group: Q
        cp_tile_kv(stg[0], base, moff, tid);
        CP_COMMIT();                                // group: tile 0
        cp_tile_kv(stg[1], base + (size_t)KT_ * D_, moff + KT_, tid);
        CP_COMMIT();                                // group: tile 1
        cp_tile_kv(stg[2], base + (size_t)2 * KT_ * D_, moff + 2 * KT_, tid);
        CP_COMMIT();                                // group: tile 2
    }
    CP_WAIT(3);                                     // Q arrived
    __syncthreads();

    // Q fragments (fp16)
    uint32_t aH[4][4];
    {
        int r = wid * 16 + (lane & 15);
        int ch = (lane >> 4) * 8;
        const __half* sQ = (const __half*)(smem + SQ_OFF);
#pragma unroll
        for (int ds = 0; ds < 4; ds++)
            ldsm_x4(aH[ds], smem_u32(&sQ[r * ROWP_ + ds * 16 + ch]));
    }

    const uint32_t koff = (((lane & 7) + ((lane >> 4) << 3)) * ROWP_) * 2 + ((lane >> 3) & 1) * 16;
    const uint32_t voff = (lane & 15) * ROWP_ * 2 + (lane >> 4) * 16;
    const int rsb = ROWP_ * 2;
    const int qr0 = wid * 16 + (lane >> 2);

    // Per-row inverse rowsums (same fp16 QK as rowsum_kernel -> rows sum to 1)
    const float inv0 = g_inv[bh * S_ + qt * TQ_ + qr0];
    const float inv1 = g_inv[bh * S_ + qt * TQ_ + qr0 + 8];

    float o[8][4];
#pragma unroll
    for (int dn = 0; dn < 8; dn++)
#pragma unroll
        for (int c = 0; c < 4; c++) o[dn][c] = 0.f;

#pragma unroll 1
    for (int kt = 0; kt < NKT_; kt++) {
        const int s = kt & 3;
        CP_WAIT(2);          // tile kt arrived (kt+1, kt+2 may still fly)
        __syncthreads();     // visibility + stage (kt+3)&3 fully retired

        if (kt + 3 < NKT_)
            cp_tile_kv(stg[(kt + 3) & 3], base + (size_t)(kt + 3) * KT_ * D_,
                       moff + (kt + 3) * KT_, tid);
        CP_COMMIT();

        const uint32_t bkf = stg[s] + KF_ + koff;
        const uint32_t bvv = stg[s] + VV_ + voff;
        const float* msk = (const float*)(smem + (s * STG_SZ + MSK_));

        // QK for chunk 0 (single-term fp16)
        float c0[4] = {0.f, 0.f, 0.f, 0.f}, c1[4] = {0.f, 0.f, 0.f, 0.f};
#pragma unroll
        for (int ds = 0; ds < 4; ds++) {
            uint32_t k4[4];
            ldsm_x4(k4, bkf + ds * 32);
            mma_f16(c0, aH[ds], k4);
            mma_f16(c1, aH[ds], k4 + 2);
        }

#pragma unroll
        for (int nc = 0; nc < NCH_; nc++) {
            const int n0 = nc * 16;
            // exp + normalize (final attn values)
            float pn[2][4];
            {
                int kc = n0 + ((lane & 3) << 1);
                float m00 = msk[kc] * inv0,     m01 = msk[kc + 1] * inv0;
                float m10 = msk[kc + 8] * inv0, m11 = msk[kc + 9] * inv0;
                float n00 = msk[kc] * inv1,     n01 = msk[kc + 1] * inv1;
                float n10 = msk[kc + 8] * inv1, n11 = msk[kc + 9] * inv1;
                pn[0][0] = m00 * __expf(c0[0]);
                pn[0][1] = m01 * __expf(c0[1]);
                pn[0][2] = n00 * __expf(c0[2]);
                pn[0][3] = n01 * __expf(c0[3]);
                pn[1][0] = m10 * __expf(c1[0]);
                pn[1][1] = m11 * __expf(c1[1]);
                pn[1][2] = n10 * __expf(c1[2]);
                pn[1][3] = n11 * __expf(c1[3]);
            }

            // QK for chunk nc+1 (covers exp latency)
            if (nc < NCH_ - 1) {
#pragma unroll
                for (int i = 0; i < 4; i++) { c0[i] = 0.f; c1[i] = 0.f; }
#pragma unroll
                for (int ds = 0; ds < 4; ds++) {
                    uint32_t k4[4];
                    ldsm_x4(k4, bkf + (n0 + 16) * rsb + ds * 32);
                    mma_f16(c0, aH[ds], k4);
                    mma_f16(c1, aH[ds], k4 + 2);
                }
            }

            // pack normalized p (single fp16)
            uint32_t ph[4];
            ph[0] = h2_of(pn[0][0], pn[0][1]);
            ph[1] = h2_of(pn[0][2], pn[0][3]);
            ph[2] = h2_of(pn[1][0], pn[1][1]);
            ph[3] = h2_of(pn[1][2], pn[1][3]);

            // PV (single-term fp16)
#pragma unroll
            for (int dp = 0; dp < 4; dp++) {
                uint32_t v4[4];
                ldsm_x4t(v4, bvv + n0 * rsb + dp * 32);
                mma_f16(o[2 * dp],     ph, v4);
                mma_f16(o[2 * dp + 1], ph, v4 + 2);
            }

            // Final attn store (streaming: never re-read)
#pragma unroll
            for (int nt = 0; nt < 2; nt++) {
                int col = kt * KT_ + n0 + nt * 8 + ((lane & 3) << 1);
                __stwt(reinterpret_cast<float2*>(Ag + (size_t)qr0 * S_ + col),
                       make_float2(pn[nt][0], pn[nt][1]));
                __stwt(reinterpret_cast<float2*>(Ag + (size_t)(qr0 + 8) * S_ + col),
                       make_float2(pn[nt][2], pn[nt][3]));
            }
        }
    }

    // out = o (p was already normalized before PV)
#pragma unroll
    for (int dn = 0; dn < 8; dn++) {
        int col = dn * 8 + ((lane & 3) << 1);
        *reinterpret_cast<float2*>(Og + (size_t)qr0 * D_ + col) =
            make_float2(o[dn][0], o[dn][1]);
        *reinterpret_cast<float2*>(Og + (size_t)(qr0 + 8) * D_ + col) =
            make_float2(o[dn][2], o[dn][3]);
    }
}

} // namespace

extern "C" void kernel_launch(void* const* d_in, const int* in_sizes, int n_in,
                              void* d_out, int out_size) {
    (void)in_sizes; (void)n_in; (void)out_size;
    const float* q = (const float*)d_in[0];
    const float* k = (const float*)d_in[1];
    const float* v = (const float*)d_in[2];
    const int*   m = (const int*)d_in[3];
    float* out = (float*)d_out;

    convert_kernel<<<2048, 256>>>(q, k, v, m);

    cudaFuncSetAttribute(rowsum_kernel, cudaFuncAttributeMaxDynamicSharedMemorySize, RSMEM_BYTES);
    dim3 grid(S_ / TQ_, BH_);
    rowsum_kernel<<<grid, THREADS_, RSMEM_BYTES>>>();

    cudaFuncSetAttribute(attn_kernel, cudaFuncAttributeMaxDynamicSharedMemorySize, SMEM_BYTES);
    attn_kernel<<<grid, THREADS_, SMEM_BYTES>>>(out);
}

// round 15
// speedup vs baseline: 1.1340x; 1.0944x over previous
#include <cuda_runtime.h>
#include <cuda_bf16.h>
#include <cuda_fp16.h>
#include <cstdint>

// ============================================================================
// Fused SDPA with attn-matrix output.
// R15: R12 skeleton (3 stages, KT=64, Q overlay) +
//   - rowsum_kernel processes 2 q-tiles per CTA (K LDSM shared by both Q
//     fragment sets; per-tile overhead amortized; 2x accumulator ILP).
//   - attn_kernel: mask hoisted to persistent smem (loaded once), attn
//     stores use __stcs instead of __stwt.
//   convert_kernel: Q(/8),K,V -> fp16; mask -> float.
// ============================================================================

namespace {

constexpr int S_  = 2048;
constexpr int D_  = 64;
constexpr int BH_ = 32;          // B*H
constexpr int TQ_ = 128;         // queries per q-tile
constexpr int KT_ = 64;          // keys per stage
constexpr int NKT_ = S_ / KT_;   // 32 tiles
constexpr int NCH_ = KT_ / 16;   // 4 chunks per tile
constexpr int THREADS_ = 256;    // 8 warps
constexpr int ROWP_ = 72;        // padded 16-bit row (144B) -> conflict-free LDSM
constexpr int NELEM_ = BH_ * S_ * D_;   // 4.19M per tensor

// ---- scratch ----
__device__ __half g_qf[NELEM_];                 // Q/8 fp16
__device__ __half g_kf[NELEM_];                 // K fp16
__device__ __half g_v[NELEM_];                  // V fp16
__device__ float g_mf[2 * S_];
__device__ float g_inv[BH_ * S_];               // 1/rowsum per (bh, row)

// ---- attn kernel smem: 3 stages (K+V), Q overlays stage 1, mask persistent ----
constexpr int KF_  = 0;
constexpr int VV_  = KF_ + KT_ * ROWP_ * 2;          // 9216
constexpr int STG_SZ = VV_ + KT_ * ROWP_ * 2;        // 18432 (K+V only)
constexpr int SQ_OFF = STG_SZ;                       // Q fp16 = exactly stage 1
constexpr int SMSK_OFF = 3 * STG_SZ;                 // 55296 (mask: 2048 floats)
constexpr int SMEM_BYTES = SMSK_OFF + S_ * 4;        // 63488 (2 CTAs/SM fits)

// ---- rowsum kernel smem: 2 Q tiles + persistent mask + 3 K-only stages ----
constexpr int RQ_OFF = 0;                            // Q: 2*18432 = 36864
constexpr int RMSK_OFF = 2 * TQ_ * ROWP_ * 2;        // 36864 (mask 8192)
constexpr int RSTG_OFF = RMSK_OFF + S_ * 4;          // 45056
constexpr int RSTG_SZ = KT_ * ROWP_ * 2;             // 9216 (K only)
constexpr int RSMEM_BYTES = RSTG_OFF + 3 * RSTG_SZ;  // 72704 (2 CTAs/SM fits)

__device__ __forceinline__ uint32_t smem_u32(const void* p) {
    return (uint32_t)__cvta_generic_to_shared(p);
}
__device__ __forceinline__ void cp16(uint32_t dst, const void* src) {
    asm volatile("cp.async.cg.shared.global [%0], [%1], 16;" :: "r"(dst), "l"(src));
}
#define CP_COMMIT() asm volatile("cp.async.commit_group;" ::: "memory")
#define CP_WAIT(n)  asm volatile("cp.async.wait_group %0;" :: "n"(n) : "memory")

__device__ __forceinline__ void ldsm_x4(uint32_t a[4], uint32_t addr) {
    asm volatile("ldmatrix.sync.aligned.m8n8.x4.shared.b16 {%0,%1,%2,%3}, [%4];"
                 : "=r"(a[0]), "=r"(a[1]), "=r"(a[2]), "=r"(a[3]) : "r"(addr));
}
__device__ __forceinline__ void ldsm_x4t(uint32_t a[4], uint32_t addr) {
    asm volatile("ldmatrix.sync.aligned.m8n8.x4.trans.shared.b16 {%0,%1,%2,%3}, [%4];"
                 : "=r"(a[0]), "=r"(a[1]), "=r"(a[2]), "=r"(a[3]) : "r"(addr));
}
__device__ __forceinline__ void mma_f16(float c[4], const uint32_t a[4], const uint32_t b[2]) {
    asm volatile(
        "mma.sync.aligned.m16n8k16.row.col.f32.f16.f16.f32 "
        "{%0,%1,%2,%3}, {%4,%5,%6,%7}, {%8,%9}, {%0,%1,%2,%3};"
        : "+f"(c[0]), "+f"(c[1]), "+f"(c[2]), "+f"(c[3])
        : "r"(a[0]), "r"(a[1]), "r"(a[2]), "r"(a[3]), "r"(b[0]), "r"(b[1]));
}
__device__ __forceinline__ uint2 pack_f16x4(float4 v) {
    __half2 a = __floats2half2_rn(v.x, v.y);
    __half2 b = __floats2half2_rn(v.z, v.w);
    return make_uint2(*reinterpret_cast<uint32_t*>(&a), *reinterpret_cast<uint32_t*>(&b));
}
__device__ __forceinline__ uint32_t h2_of(float x, float y) {
    __half2 h = __floats2half2_rn(x, y);
    return *reinterpret_cast<uint32_t*>(&h);
}

// ---------------------------------------------------------------------------
__global__ void __launch_bounds__(256)
convert_kernel(const float* __restrict__ q, const float* __restrict__ k,
               const float* __restrict__ v, const int* __restrict__ m) {
    const int N4 = NELEM_ / 4;
    const int stride = gridDim.x * blockDim.x;
    for (int j = blockIdx.x * blockDim.x + threadIdx.x; j < N4; j += stride) {
        float4 x = reinterpret_cast<const float4*>(q)[j];
        x.x *= 0.125f; x.y *= 0.125f; x.z *= 0.125f; x.w *= 0.125f;
        reinterpret_cast<uint2*>(g_qf)[j] = pack_f16x4(x);
        reinterpret_cast<uint2*>(g_kf)[j] = pack_f16x4(reinterpret_cast<const float4*>(k)[j]);
        reinterpret_cast<uint2*>(g_v)[j]  = pack_f16x4(reinterpret_cast<const float4*>(v)[j]);
    }
    for (int j = blockIdx.x * blockDim.x + threadIdx.x; j < 2 * S_; j += stride)
        g_mf[j] = m[j] ? 1.f : 0.f;
}

// ---------------------------------------------------------------------------
// rowsum_kernel: 2 q-tiles per CTA. fp16 QK -> exp -> rowsum -> 1/rowsum.
// K tile fragments are loaded once per chunk and reused by both Q sets.
// ---------------------------------------------------------------------------
__device__ __forceinline__ void cp_tile_k(uint32_t stg, size_t kvoff, int tid) {
#pragma unroll
    for (int i = 0; i < 2; i++) {
        int c = tid + THREADS_ * i;                 // 0..511 (64 rows x 8 chunks)
        int row = c >> 3, j = c & 7;
        cp16(stg + row * 144 + j * 16, g_kf + kvoff + row * 64 + j * 8);
    }
}

__global__ void __launch_bounds__(THREADS_, 2)
rowsum_kernel() {
    extern __shared__ char smem[];
    const uint32_t sb = smem_u32(smem);

    const int qt0 = blockIdx.x * 2;      // first of two q-tiles
    const int bh = blockIdx.y;
    const int tid = threadIdx.x;
    const int wid = tid >> 5;
    const int lane = tid & 31;
    const int b = bh >> 4;

    const size_t base = (size_t)bh * S_ * D_;
    const size_t qoff = base + (size_t)qt0 * TQ_ * D_;   // 256 Q rows
    const size_t moff = (size_t)b * S_;

    const uint32_t stg[3] = {sb + RSTG_OFF, sb + RSTG_OFF + RSTG_SZ,
                             sb + RSTG_OFF + 2 * RSTG_SZ};

    // Prologue: Q (2 tiles, 2048 chunks) + mask (512 chunks) + K tiles 0,1
    {
#pragma unroll
        for (int i = 0; i < 8; i++) {
            int c = tid + THREADS_ * i;             // 0..2047
            int row = c >> 3, j = c & 7;
            cp16(sb + RQ_OFF + row * 144 + j * 16, g_qf + qoff + row * 64 + j * 8);
        }
#pragma unroll
        for (int i = 0; i < 2; i++) {
            int c = tid + THREADS_ * i;             // 0..511
            cp16(sb + RMSK_OFF + c * 16, g_mf + moff + c * 4);
        }
        CP_COMMIT();                                // group: Q + mask
        cp_tile_k(stg[0], base, tid);
        CP_COMMIT();                                // group: tile 0
        cp_tile_k(stg[1], base + KT_ * D_, tid);
        CP_COMMIT();                                // group: tile 1
    }
    CP_WAIT(2);                                     // Q + mask arrived
    __syncthreads();

    // Q fragments: two sets (u = q-tile within CTA)
    uint32_t qf[2][4][4];
    {
        int ch = (lane >> 4) * 8;
        const __half* sQ = (const __half*)(smem + RQ_OFF);
#pragma unroll
        for (int u = 0; u < 2; u++) {
            int r = u * TQ_ + wid * 16 + (lane & 15);
#pragma unroll
            for (int ds = 0; ds < 4; ds++)
                ldsm_x4(qf[u][ds], smem_u32(&sQ[r * ROWP_ + ds * 16 + ch]));
        }
    }

    const uint32_t koff = (((lane & 7) + ((lane >> 4) << 3)) * ROWP_) * 2 + ((lane >> 3) & 1) * 16;
    const int rsb = ROWP_ * 2;
    const float* maskp = (const float*)(smem + RMSK_OFF);

    float rs0[2] = {0.f, 0.f}, rs1[2] = {0.f, 0.f};

    int s = 0, sp2 = 2;
#pragma unroll 1
    for (int kt = 0; kt < NKT_; kt++) {
        if (kt > 0) { CP_WAIT(1); __syncthreads(); }
        if (kt + 2 < NKT_)
            cp_tile_k(stg[sp2], base + (size_t)(kt + 2) * KT_ * D_, tid);
        CP_COMMIT();

        const uint32_t bkf = stg[s] + koff;
        const float* msk = maskp + kt * KT_;

#pragma unroll
        for (int nc = 0; nc < NCH_; nc++) {
            const int n0 = nc * 16;
            uint32_t k4[4][4];
#pragma unroll
            for (int ds = 0; ds < 4; ds++)
                ldsm_x4(k4[ds], bkf + n0 * rsb + ds * 32);
            int kc = n0 + ((lane & 3) << 1);
            float m00 = msk[kc],     m01 = msk[kc + 1];
            float m10 = msk[kc + 8], m11 = msk[kc + 9];
#pragma unroll
            for (int u = 0; u < 2; u++) {
                float c0[4] = {0.f, 0.f, 0.f, 0.f};
                float c1[4] = {0.f, 0.f, 0.f, 0.f};
#pragma unroll
                for (int ds = 0; ds < 4; ds++) {
                    mma_f16(c0, qf[u][ds], k4[ds]);
                    mma_f16(c1, qf[u][ds], k4[ds] + 2);
                }
                rs0[u] += m00 * __expf(c0[0]) + m01 * __expf(c0[1])
                        + m10 * __expf(c1[0]) + m11 * __expf(c1[1]);
                rs1[u] += m00 * __expf(c0[2]) + m01 * __expf(c0[3])
                        + m10 * __expf(c1[2]) + m11 * __expf(c1[3]);
            }
        }
        sp2 = s;
        s = (s == 2) ? 0 : s + 1;
    }

#pragma unroll
    for (int u = 0; u < 2; u++) {
        float a = rs0[u], c = rs1[u];
        a += __shfl_xor_sync(0xffffffffu, a, 1);
        a += __shfl_xor_sync(0xffffffffu, a, 2);
        c += __shfl_xor_sync(0xffffffffu, c, 1);
        c += __shfl_xor_sync(0xffffffffu, c, 2);
        if ((lane & 3) == 0) {
            int r = (qt0 + u) * TQ_ + wid * 16 + (lane >> 2);
            g_inv[bh * S_ + r]     = 1.f / a;
            g_inv[bh * S_ + r + 8] = 1.f / c;
        }
    }
}

// ---------------------------------------------------------------------------
// Main attention kernel: 3-stage pipeline, persistent mask, __stcs stores.
// ---------------------------------------------------------------------------
__device__ __forceinline__ void cp_tile_kv(uint32_t stg, size_t kvoff, int tid) {
#pragma unroll
    for (int i = 0; i < 2; i++) {
        int c = tid + THREADS_ * i;                 // 0..511
        int row = c >> 3, j = c & 7;
        uint32_t so = row * 144 + j * 16;
        size_t go = kvoff + row * 64 + j * 8;
        cp16(stg + KF_ + so, g_kf + go);
        cp16(stg + VV_ + so, g_v + go);
    }
}

__global__ void __launch_bounds__(THREADS_, 2)
attn_kernel(float* __restrict__ Out) {
    extern __shared__ char smem[];
    const uint32_t sb = smem_u32(smem);

    const int qt = blockIdx.x;
    const int bh = blockIdx.y;
    const int tid = threadIdx.x;
    const int wid = tid >> 5;
    const int lane = tid & 31;
    const int b = bh >> 4;

    const size_t base = (size_t)bh * S_ * D_;
    const size_t qoff = base + (size_t)qt * TQ_ * D_;
    const size_t moff = (size_t)b * S_;
    float* Og = Out + qoff;
    float* Ag = Out + (size_t)BH_ * S_ * D_ + (size_t)bh * S_ * S_ + (size_t)qt * TQ_ * S_;

    const uint32_t stg[3] = {sb, sb + STG_SZ, sb + 2 * STG_SZ};

    // Prologue: Q (overlaying stage 1) + mask (persistent), tile 0
    {
#pragma unroll
        for (int i = 0; i < 4; i++) {
            int c = tid + THREADS_ * i;             // 0..1023
            int row = c >> 3, j = c & 7;
            cp16(sb + SQ_OFF + row * 144 + j * 16, g_qf + qoff + row * 64 + j * 8);
        }
#pragma unroll
        for (int i = 0; i < 2; i++) {
            int c = tid + THREADS_ * i;             // 0..511
            cp16(sb + SMSK_OFF + c * 16, g_mf + moff + c * 4);
        }
        CP_COMMIT();                                // group: Q + mask
        cp_tile_kv(stg[0], base, tid);
        CP_COMMIT();                                // group: tile 0
    }
    CP_WAIT(1);                                     // Q + mask arrived
    __syncthreads();

    // Q fragments (fp16)
    uint32_t aH[4][4];
    {
        int r = wid * 16 + (lane & 15);
        int ch = (lane >> 4) * 8;
        const __half* sQ = (const __half*)(smem + SQ_OFF);
#pragma unroll
        for (int ds = 0; ds < 4; ds++)
            ldsm_x4(aH[ds], smem_u32(&sQ[r * ROWP_ + ds * 16 + ch]));
    }
    __syncthreads();    // stage 1 free
    cp_tile_kv(stg[1], base + KT_ * D_, tid);
    CP_COMMIT();                                    // group: tile 1

    const uint32_t koff = (((lane & 7) + ((lane >> 4) << 3)) * ROWP_) * 2 + ((lane >> 3) & 1) * 16;
    const uint32_t voff = (lane & 15) * ROWP_ * 2 + (lane >> 4) * 16;
    const int rsb = ROWP_ * 2;
    const int qr0 = wid * 16 + (lane >> 2);
    const float* maskp = (const float*)(smem + SMSK_OFF);

    // Per-row inverse rowsums (same fp16 QK as rowsum_kernel -> rows sum to 1)
    const float inv0 = g_inv[bh * S_ + qt * TQ_ + qr0];
    const float inv1 = g_inv[bh * S_ + qt * TQ_ + qr0 + 8];

    float o[8][4];
#pragma unroll
    for (int dn = 0; dn < 8; dn++)
#pragma unroll
        for (int c = 0; c < 4; c++) o[dn][c] = 0.f;

    int s = 0, sp2 = 2;
#pragma unroll 1
    for (int kt = 0; kt < NKT_; kt++) {
        CP_WAIT(1);
        __syncthreads();

        if (kt + 2 < NKT_)
            cp_tile_kv(stg[sp2], base + (size_t)(kt + 2) * KT_ * D_, tid);
        CP_COMMIT();

        const uint32_t bkf = stg[s] + KF_ + koff;
        const uint32_t bvv = stg[s] + VV_ + voff;
        const float* msk = maskp + kt * KT_;

        // QK for chunk 0 (single-term fp16)
        float c0[4] = {0.f, 0.f, 0.f, 0.f}, c1[4] = {0.f, 0.f, 0.f, 0.f};
#pragma unroll
        for (int ds = 0; ds < 4; ds++) {
            uint32_t k4[4];
            ldsm_x4(k4, bkf + ds * 32);
            mma_f16(c0, aH[ds], k4);
            mma_f16(c1, aH[ds], k4 + 2);
        }

#pragma unroll
        for (int nc = 0; nc < NCH_; nc++) {
            const int n0 = nc * 16;
            // exp + normalize (final attn values)
            float pn[2][4];
            {
                int kc = n0 + ((lane & 3) << 1);
                float m00 = msk[kc] * inv0,     m01 = msk[kc + 1] * inv0;
                float m10 = msk[kc + 8] * inv0, m11 = msk[kc + 9] * inv0;
                float n00 = msk[kc] * inv1,     n01 = msk[kc + 1] * inv1;
                float n10 = msk[kc + 8] * inv1, n11 = msk[kc + 9] * inv1;
                pn[0][0] = m00 * __expf(c0[0]);
                pn[0][1] = m01 * __expf(c0[1]);
                pn[0][2] = n00 * __expf(c0[2]);
                pn[0][3] = n01 * __expf(c0[3]);
                pn[1][0] = m10 * __expf(c1[0]);
                pn[1][1] = m11 * __expf(c1[1]);
                pn[1][2] = n10 * __expf(c1[2]);
                pn[1][3] = n11 * __expf(c1[3]);
            }

            // QK for chunk nc+1 (covers exp latency)
            if (nc < NCH_ - 1) {
#pragma unroll
                for (int i = 0; i < 4; i++) { c0[i] = 0.f; c1[i] = 0.f; }
#pragma unroll
                for (int ds = 0; ds < 4; ds++) {
                    uint32_t k4[4];
                    ldsm_x4(k4, bkf + (n0 + 16) * rsb + ds * 32);
                    mma_f16(c0, aH[ds], k4);
                    mma_f16(c1, aH[ds], k4 + 2);
                }
            }

            // pack normalized p (single fp16)
            uint32_t ph[4];
            ph[0] = h2_of(pn[0][0], pn[0][1]);
            ph[1] = h2_of(pn[0][2], pn[0][3]);
            ph[2] = h2_of(pn[1][0], pn[1][1]);
            ph[3] = h2_of(pn[1][2], pn[1][3]);

            // PV (single-term fp16)
#pragma unroll
            for (int dp = 0; dp < 4; dp++) {
                uint32_t v4[4];
                ldsm_x4t(v4, bvv + n0 * rsb + dp * 32);
                mma_f16(o[2 * dp],     ph, v4);
                mma_f16(o[2 * dp + 1], ph, v4 + 2);
            }

            // Final attn store (streaming eviction: never re-read)
#pragma unroll
            for (int nt = 0; nt < 2; nt++) {
                int col = kt * KT_ + n0 + nt * 8 + ((lane & 3) << 1);
                __stcs(reinterpret_cast<float2*>(Ag + (size_t)qr0 * S_ + col),
                       make_float2(pn[nt][0], pn[nt][1]));
                __stcs(reinterpret_cast<float2*>(Ag + (size_t)(qr0 + 8) * S_ + col),
                       make_float2(pn[nt][2], pn[nt][3]));
            }
        }

        sp2 = s;
        s = (s == 2) ? 0 : s + 1;
    }

    // out = o (p was already normalized before PV)
#pragma unroll
    for (int dn = 0; dn < 8; dn++) {
        int col = dn * 8 + ((lane & 3) << 1);
        *reinterpret_cast<float2*>(Og + (size_t)qr0 * D_ + col) =
            make_float2(o[dn][0], o[dn][1]);
        *reinterpret_cast<float2*>(Og + (size_t)(qr0 + 8) * D_ + col) =
            make_float2(o[dn][2], o[dn][3]);
    }
}

} // namespace

extern "C" void kernel_launch(void* const* d_in, const int* in_sizes, int n_in,
                              void* d_out, int out_size) {
    (void)in_sizes; (void)n_in; (void)out_size;
    const float* q = (const float*)d_in[0];
    const float* k = (const float*)d_in[1];
    const float* v = (const float*)d_in[2];
    const int*   m = (const int*)d_in[3];
    float* out = (float*)d_out;

    convert_kernel<<<2048, 256>>>(q, k, v, m);

    cudaFuncSetAttribute(rowsum_kernel, cudaFuncAttributeMaxDynamicSharedMemorySize, RSMEM_BYTES);
    dim3 rgrid(S_ / (2 * TQ_), BH_);   // 2 q-tiles per CTA
    rowsum_kernel<<<rgrid, THREADS_, RSMEM_BYTES>>>();

    cudaFuncSetAttribute(attn_kernel, cudaFuncAttributeMaxDynamicSharedMemorySize, SMEM_BYTES);
    dim3 grid(S_ / TQ_, BH_);
    attn_kernel<<<grid, THREADS_, SMEM_BYTES>>>(out);
}